// round 9
// baseline (speedup 1.0000x reference)
#include <cuda_runtime.h>
#include <cstdint>

namespace {

constexpr int kB = 64;
constexpr int kN = 8;
constexpr int kV = 128000;
constexpr int kTPB = 128;
constexpr int kGrid = 148 * 16;            // exactly one resident wave (<=32 regs)
constexpr int kRows = 2 * kB;              // 64 bonus rows + 64 recover rows
constexpr int kJPerRow = kV / 4 / 256;     // 125 items per row (item = 256 float4)
constexpr int kItems = kRows * kJPerRow;   // 16000

// packed argmax: (float_bits << 32) | ~index  -> atomicMax == (max val, tie: min idx)
__device__ unsigned long long g_best[kRows];
__device__ unsigned g_ticket;

__device__ __forceinline__ float neg_inf() { return __int_as_float(0xff800000); }

// ---------------- JAX threefry2x32 (exact round structure) -------------------------
__device__ __forceinline__ void tfround(uint32_t& x0, uint32_t& x1, int r) {
  x0 += x1;
  x1 = __funnelshift_l(x1, x1, r);
  x1 ^= x0;
}

__device__ __forceinline__ uint2 threefry2x32(uint32_t k0, uint32_t k1,
                                              uint32_t x0, uint32_t x1) {
  uint32_t k2 = k0 ^ k1 ^ 0x1BD11BDAu;
  x0 += k0; x1 += k1;
  tfround(x0, x1, 13); tfround(x0, x1, 15); tfround(x0, x1, 26); tfround(x0, x1, 6);
  x0 += k1; x1 += k2 + 1u;
  tfround(x0, x1, 17); tfround(x0, x1, 29); tfround(x0, x1, 16); tfround(x0, x1, 24);
  x0 += k2; x1 += k0 + 2u;
  tfround(x0, x1, 13); tfround(x0, x1, 15); tfround(x0, x1, 26); tfround(x0, x1, 6);
  x0 += k0; x1 += k1 + 3u;
  tfround(x0, x1, 17); tfround(x0, x1, 29); tfround(x0, x1, 16); tfround(x0, x1, 24);
  x0 += k1; x1 += k2 + 4u;
  tfround(x0, x1, 13); tfround(x0, x1, 15); tfround(x0, x1, 26); tfround(x0, x1, 6);
  x0 += k2; x1 += k0 + 5u;
  return make_uint2(x0, x1);
}

__device__ __forceinline__ uint32_t rbits32(uint2 key, uint32_t idx) {
  uint2 o = threefry2x32(key.x, key.y, 0u, idx);
  return o.x ^ o.y;
}

__device__ __forceinline__ float uni01(uint32_t bits) {
  return __uint_as_float((bits >> 9) | 0x3f800000u) - 1.0f;
}

// t = -log(u), u = B-1, B in [1,2). Dual path (validated rel_err 0.0 in R8):
//   d = 2-B <= 0.125: degree-6 Taylor of -log(1-d)/d, rel err ~3e-7.
//   else: -__logf(u), t >= 0.1335 -> rel err <= 1.3e-6.
__device__ __forceinline__ float tval(uint2 key, uint32_t idx) {
  uint32_t bits = rbits32(key, idx);
  float B = __uint_as_float((bits >> 9) | 0x3f800000u);
  float u = B - 1.0f;
  float d = 2.0f - B;
  float p = 0.14285714f;
  p = fmaf(p, d, 0.16666667f);
  p = fmaf(p, d, 0.2f);
  p = fmaf(p, d, 0.25f);
  p = fmaf(p, d, 0.33333333f);
  p = fmaf(p, d, 0.5f);
  p = fmaf(p, d, 1.0f);
  float ts = d * p;
  float tb = -__logf(u);
  return (d <= 0.125f) ? ts : tb;
}

struct BestPair { float v; int i; };

// Strict-'>' pairwise tree over 8 candidates: v[0..3] -> iA+{0..3},
// v[4..7] -> iB+{0..3}, iA+3 < iB. Lowest index wins ties at every level.
__device__ __forceinline__ void upd8(BestPair& best, const float* v, int iA, int iB) {
  float a0 = v[0]; int j0 = iA;
  if (v[1] > a0) { a0 = v[1]; j0 = iA + 1; }
  float a1 = v[2]; int j1 = iA + 2;
  if (v[3] > a1) { a1 = v[3]; j1 = iA + 3; }
  float a2 = v[4]; int j2 = iB;
  if (v[5] > a2) { a2 = v[5]; j2 = iB + 1; }
  float a3 = v[6]; int j3 = iB + 2;
  if (v[7] > a3) { a3 = v[7]; j3 = iB + 3; }
  if (a1 > a0) { a0 = a1; j0 = j1; }
  if (a3 > a2) { a2 = a3; j2 = j3; }
  if (a2 > a0) { a0 = a2; j0 = j2; }
  if (a0 > best.v) { best.v = a0; best.i = j0; }
}

// Block argmax (128 threads, tie-break min index); thread 0 holds the result.
// Leading __syncthreads protects the shared slots across back-to-back calls.
__device__ __forceinline__ BestPair block_argmax(BestPair best) {
  __shared__ float sv[4];
  __shared__ int   si[4];
  __syncthreads();
  unsigned full = 0xffffffffu;
#pragma unroll
  for (int off = 16; off > 0; off >>= 1) {
    float ov = __shfl_down_sync(full, best.v, off);
    int   oi = __shfl_down_sync(full, best.i, off);
    if (ov > best.v || (ov == best.v && oi < best.i)) { best.v = ov; best.i = oi; }
  }
  int warp = threadIdx.x >> 5;
  int lane = threadIdx.x & 31;
  if (lane == 0) { sv[warp] = best.v; si[warp] = best.i; }
  __syncthreads();
  if (threadIdx.x == 0) {
#pragma unroll
    for (int w = 1; w < 4; w++) {
      if (sv[w] > best.v || (sv[w] == best.v && si[w] < best.i)) {
        best.v = sv[w]; best.i = si[w];
      }
    }
  }
  return best;
}

__device__ __forceinline__ void flush_row(int row, BestPair best) {
  best = block_argmax(best);
  if (threadIdx.x == 0 && best.i != 0x7fffffff) {
    unsigned long long packed =
        ((unsigned long long)__float_as_uint(best.v) << 32) | (unsigned)(~best.i);
    atomicMax(&g_best[row], packed);
  }
}

// accept decision for (b, n)
__device__ __forceinline__ bool accept_bn(int b, int n, const int* __restrict__ tok,
                                          const float* __restrict__ dp,
                                          const float* __restrict__ vp) {
  uint2 ku = threefry2x32(0u, 1u, 0u, 0u);   // split(key(1),3)[0] — const-folded
  int L = b * kN + n;
  float u = uni01(rbits32(ku, (uint32_t)L));
  int t = tok[L];
  t = min(max(t, 0), kV - 1);
  float q = dp[(size_t)L * kV + t];
  float p = vp[((size_t)b * (kN + 1) + n) * kV + t];
  return (u * q < p);
}

// ---------------- Single mega kernel, one balanced wave ----------------------------
// Flattened work: item i -> row = i/125, j = i%125. Rows 0..63: bonus (batch=row).
// Rows 64..127: recover (batch=row-64; em self-computed; em==8 rows are no-ops).
// Each item = 256 float4 = 1024 elements; thread t handles f4 j*256+t and +128.
__global__ __launch_bounds__(kTPB, 16)
void kMega(const int* __restrict__ tok, const float* __restrict__ dp,
           const float* __restrict__ vp, float* __restrict__ out, int out_size) {
  __shared__ int s_em;
  int blk = blockIdx.x;
  int t = threadIdx.x;
  int beg = (int)((long long)blk * kItems / kGrid);
  int end = (int)((long long)(blk + 1) * kItems / kGrid);

  BestPair best = {neg_inf(), 0x7fffffff};
  int curRow = -1;
  int curEm = 0;
  const float4* rowP = nullptr;   // prob row (bonus: verify[:,N]; recover: verify[:,em])
  const float4* rowD = nullptr;   // draft row (recover only)
  uint2 key = make_uint2(0u, 0u);
  uint32_t Lbase = 0;

  for (int i = beg; i < end; i++) {
    int row = i / kJPerRow;
    int j = i - row * kJPerRow;
    if (row != curRow) {                       // block-uniform branch
      if (curRow >= 0) flush_row(curRow, best);
      best.v = neg_inf(); best.i = 0x7fffffff;
      curRow = row;
      if (row < kB) {
        key = threefry2x32(0u, 1u, 0u, 2u);    // subkey 2 (const-folded)
        rowP = (const float4*)(vp + ((size_t)row * (kN + 1) + kN) * kV);
        Lbase = (uint32_t)row * (uint32_t)kV;  // gumbel shape (B, V)
        curEm = -1;
      } else {
        int b = row - kB;
        if (t < 8) {
          bool acc = accept_bn(b, t, tok, dp, vp);
          unsigned m = __ballot_sync(0xffu, acc);
          if (t == 0) s_em = __ffs((~m) & 0x1FF) - 1;
        }
        __syncthreads();
        curEm = s_em;
        if (curEm < kN) {
          key = threefry2x32(0u, 1u, 0u, 1u);  // subkey 1 (const-folded)
          rowD = (const float4*)(dp + ((size_t)b * kN + curEm) * kV);
          rowP = (const float4*)(vp + ((size_t)b * (kN + 1) + curEm) * kV);
          Lbase = (uint32_t)(b * kN + curEm) * (uint32_t)kV;  // shape (B, N, V)
        }
      }
    }
    if (curRow >= kB && curEm >= kN) continue; // skipped recover row (uniform)

    int f0 = j * 256 + t;
    int f1 = f0 + kTPB;
    float vals[8];
    if (curRow < kB) {
      float4 pa = rowP[f0];
      float4 pb = rowP[f1];
      vals[0] = __fdividef(pa.x, tval(key, Lbase + 4 * f0 + 0));
      vals[1] = __fdividef(pa.y, tval(key, Lbase + 4 * f0 + 1));
      vals[2] = __fdividef(pa.z, tval(key, Lbase + 4 * f0 + 2));
      vals[3] = __fdividef(pa.w, tval(key, Lbase + 4 * f0 + 3));
      vals[4] = __fdividef(pb.x, tval(key, Lbase + 4 * f1 + 0));
      vals[5] = __fdividef(pb.y, tval(key, Lbase + 4 * f1 + 1));
      vals[6] = __fdividef(pb.z, tval(key, Lbase + 4 * f1 + 2));
      vals[7] = __fdividef(pb.w, tval(key, Lbase + 4 * f1 + 3));
    } else {
      float4 da = rowD[f0];
      float4 va = rowP[f0];
      float4 db = rowD[f1];
      float4 vb = rowP[f1];
      vals[0] = __fdividef(fmaxf(va.x - da.x, 0.0f), tval(key, Lbase + 4 * f0 + 0));
      vals[1] = __fdividef(fmaxf(va.y - da.y, 0.0f), tval(key, Lbase + 4 * f0 + 1));
      vals[2] = __fdividef(fmaxf(va.z - da.z, 0.0f), tval(key, Lbase + 4 * f0 + 2));
      vals[3] = __fdividef(fmaxf(va.w - da.w, 0.0f), tval(key, Lbase + 4 * f0 + 3));
      vals[4] = __fdividef(fmaxf(vb.x - db.x, 0.0f), tval(key, Lbase + 4 * f1 + 0));
      vals[5] = __fdividef(fmaxf(vb.y - db.y, 0.0f), tval(key, Lbase + 4 * f1 + 1));
      vals[6] = __fdividef(fmaxf(vb.z - db.z, 0.0f), tval(key, Lbase + 4 * f1 + 2));
      vals[7] = __fdividef(fmaxf(vb.w - db.w, 0.0f), tval(key, Lbase + 4 * f1 + 3));
    }
    upd8(best, vals, 4 * f0, 4 * f1);
  }
  if (curRow >= 0) flush_row(curRow, best);

  // ---- deterministic last-block final assembly -----------------------------------
  __threadfence();
  __shared__ bool amLast;
  if (t == 0) {
    unsigned tk = atomicAdd(&g_ticket, 1u);
    amLast = (tk == (unsigned)(kGrid - 1));
  }
  __syncthreads();
  if (!amLast) return;

  volatile unsigned long long* vbest = g_best;
  int bb = t;
  if (bb < kB) {
    int acc = 0, em = 0;
    bool alive = true;
#pragma unroll
    for (int n = 0; n < kN; n++) {
      bool a = accept_bn(bb, n, tok, dp, vp);
      acc += a ? 1 : 0;
      if (alive) { if (a) em++; else alive = false; }
    }
    if (out_size >= kB * (kN + 1) + 2 * kB) {
      out[kB * (kN + 1) + bb] = (float)acc;
      out[kB * (kN + 1) + kB + bb] = (float)em;
    }
    unsigned long long packedB = vbest[bb];
    unsigned long long packedR = vbest[kB + bb];
    int fin = (em < kN) ? (int)(~(unsigned)(packedR & 0xffffffffu))
                        : (int)(~(unsigned)(packedB & 0xffffffffu));
#pragma unroll
    for (int pos = 0; pos < kN + 1; pos++) {
      float o;
      if (pos < em)       o = (float)tok[bb * kN + pos];
      else if (pos == em) o = (float)fin;
      else                o = -1.0f;
      out[bb * (kN + 1) + pos] = o;
    }
  }
  __syncthreads();
  // reset scratch for the next graph replay
  if (t < kRows) g_best[t] = 0ull;
  if (t == 0) g_ticket = 0u;
}

}  // namespace

extern "C" void kernel_launch(void* const* d_in, const int* in_sizes, int n_in,
                              void* d_out, int out_size) {
  const int*   tok = nullptr;
  const float* dp  = nullptr;
  const float* vp  = nullptr;
  for (int i = 0; i < n_in; i++) {
    if (in_sizes[i] == kB * kN)                      tok = (const int*)d_in[i];
    else if (in_sizes[i] == kB * kN * kV)            dp  = (const float*)d_in[i];
    else if (in_sizes[i] == kB * (kN + 1) * kV)      vp  = (const float*)d_in[i];
  }
  float* out = (float*)d_out;

  kMega<<<kGrid, kTPB>>>(tok, dp, vp, out, out_size);
}